// round 1
// baseline (speedup 1.0000x reference)
#include <cuda_runtime.h>

#define D 1024
#define D4 (D / 4)
#define NB_SUM 512
#define LN_EPS 1e-5f

// Scratch (allocation-free): partial column sums transposed [col][block],
// plus the tiny staged vectors for the GEMV chain.
__device__ float g_partial[D * NB_SUM];
__device__ float g_mean[D];
__device__ float g_global[D];
__device__ float g_v[D];
__device__ float g_attn[D];

// ---------------------------------------------------------------------------
// Kernel 1: per-block partial column sums over the virtual concat of h0..h3.
// 256 threads, each owns 4 consecutive columns (one float4). Blocks take
// contiguous row chunks for coalesced, streaming reads.
// ---------------------------------------------------------------------------
__global__ void colsum_kernel(const float* __restrict__ h0, const float* __restrict__ h1,
                              const float* __restrict__ h2, const float* __restrict__ h3,
                              int n0, int n1, int n2, int n3) {
    const int total = n0 + n1 + n2 + n3;
    const int rows_per_block = (total + gridDim.x - 1) / gridDim.x;
    const int r_begin = blockIdx.x * rows_per_block;
    const int r_end   = min(r_begin + rows_per_block, total);

    const int c4 = threadIdx.x;  // float4 column index 0..255
    float4 acc = make_float4(0.f, 0.f, 0.f, 0.f);

    for (int r = r_begin; r < r_end; ++r) {
        const float* p;
        int rr;
        if (r < n0)                { p = h0; rr = r; }
        else if (r < n0 + n1)      { p = h1; rr = r - n0; }
        else if (r < n0 + n1 + n2) { p = h2; rr = r - n0 - n1; }
        else                       { p = h3; rr = r - n0 - n1 - n2; }
        float4 v = reinterpret_cast<const float4*>(p + (size_t)rr * D)[c4];
        acc.x += v.x; acc.y += v.y; acc.z += v.z; acc.w += v.w;
    }

    const int col = c4 * 4;
    g_partial[(size_t)(col + 0) * NB_SUM + blockIdx.x] = acc.x;
    g_partial[(size_t)(col + 1) * NB_SUM + blockIdx.x] = acc.y;
    g_partial[(size_t)(col + 2) * NB_SUM + blockIdx.x] = acc.z;
    g_partial[(size_t)(col + 3) * NB_SUM + blockIdx.x] = acc.w;
}

// ---------------------------------------------------------------------------
// Kernel 2: reduce partials -> mean. One block per column; reads are
// contiguous thanks to the transposed partial layout.
// ---------------------------------------------------------------------------
__global__ void reduce_kernel(int total_rows) {
    const int col = blockIdx.x;
    const int tid = threadIdx.x;  // 256 threads
    float s = 0.f;
    for (int i = tid; i < NB_SUM; i += 256)
        s += g_partial[(size_t)col * NB_SUM + i];

    // warp reduce
    #pragma unroll
    for (int o = 16; o > 0; o >>= 1) s += __shfl_xor_sync(0xFFFFFFFFu, s, o);

    __shared__ float ws[8];
    if ((tid & 31) == 0) ws[tid >> 5] = s;
    __syncthreads();
    if (tid == 0) {
        float t = 0.f;
        #pragma unroll
        for (int w = 0; w < 8; ++w) t += ws[w];
        g_mean[col] = t / (float)total_rows;
    }
}

// ---------------------------------------------------------------------------
// Kernel 3: GEMV  y = W @ x + b. One block (256 thr) per output row.
// stage 0: x=g_mean,   y=g_global (also written to d_out[0:1024])
// stage 1: x=g_global, y=g_v
// stage 2: x=g_v,      y=g_attn
// ---------------------------------------------------------------------------
__global__ void gemv_kernel(const float* __restrict__ W, const float* __restrict__ b,
                            int stage, float* __restrict__ out) {
    const int row = blockIdx.x;
    const int tid = threadIdx.x;
    const float* x = (stage == 0) ? g_mean : (stage == 1) ? g_global : g_v;
    float*       y = (stage == 0) ? g_global : (stage == 1) ? g_v : g_attn;

    const float4* Wr = reinterpret_cast<const float4*>(W + (size_t)row * D);
    const float4* xv = reinterpret_cast<const float4*>(x);

    float s = 0.f;
    for (int i = tid; i < D4; i += 256) {
        float4 w = Wr[i];
        float4 xx = xv[i];
        s += w.x * xx.x + w.y * xx.y + w.z * xx.z + w.w * xx.w;
    }
    #pragma unroll
    for (int o = 16; o > 0; o >>= 1) s += __shfl_xor_sync(0xFFFFFFFFu, s, o);

    __shared__ float ws[8];
    if ((tid & 31) == 0) ws[tid >> 5] = s;
    __syncthreads();
    if (tid == 0) {
        float t = 0.f;
        #pragma unroll
        for (int w = 0; w < 8; ++w) t += ws[w];
        t += b[row];
        y[row] = t;
        if (stage == 0) out[row] = t;  // global_vec output
    }
}

// ---------------------------------------------------------------------------
// Kernel 4: LayerNorm(h + attn) for every row. Warp-per-row: 32 lanes x
// 8 float4 each = 1024 elems; pure shuffle reduction, no block barriers.
// 8 warps (8 rows) per 256-thread block.
// ---------------------------------------------------------------------------
__global__ void ln_kernel(const float* __restrict__ h0, const float* __restrict__ h1,
                          const float* __restrict__ h2, const float* __restrict__ h3,
                          int n0, int n1, int n2, int n3,
                          const float* __restrict__ gamma, const float* __restrict__ beta,
                          float* __restrict__ out) {
    const int warp = threadIdx.x >> 5;
    const int lane = threadIdx.x & 31;
    const int total = n0 + n1 + n2 + n3;
    const int g = blockIdx.x * 8 + warp;   // global row
    if (g >= total) return;

    const float* p;
    int rr;
    if (g < n0)                { p = h0; rr = g; }
    else if (g < n0 + n1)      { p = h1; rr = g - n0; }
    else if (g < n0 + n1 + n2) { p = h2; rr = g - n0 - n1; }
    else                       { p = h3; rr = g - n0 - n1 - n2; }

    const float4* row  = reinterpret_cast<const float4*>(p + (size_t)rr * D);
    const float4* attn = reinterpret_cast<const float4*>(g_attn);

    float4 xs[8];
    float sum = 0.f, sumsq = 0.f;
    #pragma unroll
    for (int k = 0; k < 8; ++k) {
        const int idx = lane + 32 * k;
        float4 v = row[idx];
        float4 a = attn[idx];
        v.x += a.x; v.y += a.y; v.z += a.z; v.w += a.w;
        xs[k] = v;
        sum   += v.x + v.y + v.z + v.w;
        sumsq += v.x * v.x + v.y * v.y + v.z * v.z + v.w * v.w;
    }
    #pragma unroll
    for (int o = 16; o > 0; o >>= 1) {
        sum   += __shfl_xor_sync(0xFFFFFFFFu, sum,   o);
        sumsq += __shfl_xor_sync(0xFFFFFFFFu, sumsq, o);
    }

    const float inv_d = 1.f / (float)D;
    const float mean = sum * inv_d;
    const float var  = sumsq * inv_d - mean * mean;
    const float rstd = rsqrtf(var + LN_EPS);

    const float4* gm4 = reinterpret_cast<const float4*>(gamma);
    const float4* bt4 = reinterpret_cast<const float4*>(beta);
    float4* orow = reinterpret_cast<float4*>(out + D + (size_t)g * D);

    #pragma unroll
    for (int k = 0; k < 8; ++k) {
        const int idx = lane + 32 * k;
        float4 gmv = gm4[idx];
        float4 btv = bt4[idx];
        float4 v = xs[k];
        v.x = (v.x - mean) * rstd * gmv.x + btv.x;
        v.y = (v.y - mean) * rstd * gmv.y + btv.y;
        v.z = (v.z - mean) * rstd * gmv.z + btv.z;
        v.w = (v.w - mean) * rstd * gmv.w + btv.w;
        orow[idx] = v;
    }
}

extern "C" void kernel_launch(void* const* d_in, const int* in_sizes, int n_in,
                              void* d_out, int out_size) {
    const float* h0    = (const float*)d_in[0];
    const float* h1    = (const float*)d_in[1];
    const float* h2    = (const float*)d_in[2];
    const float* h3    = (const float*)d_in[3];
    const float* Wp    = (const float*)d_in[4];
    const float* bp    = (const float*)d_in[5];
    const float* Wv    = (const float*)d_in[6];
    const float* bv    = (const float*)d_in[7];
    const float* Wo    = (const float*)d_in[8];
    const float* bo    = (const float*)d_in[9];
    const float* gamma = (const float*)d_in[10];
    const float* beta  = (const float*)d_in[11];
    float* out = (float*)d_out;

    const int n0 = in_sizes[0] / D;
    const int n1 = in_sizes[1] / D;
    const int n2 = in_sizes[2] / D;
    const int n3 = in_sizes[3] / D;
    const int total = n0 + n1 + n2 + n3;

    colsum_kernel<<<NB_SUM, 256>>>(h0, h1, h2, h3, n0, n1, n2, n3);
    reduce_kernel<<<D, 256>>>(total);
    gemv_kernel<<<D, 256>>>(Wp, bp, 0, out);
    gemv_kernel<<<D, 256>>>(Wv, bv, 1, out);
    gemv_kernel<<<D, 256>>>(Wo, bo, 2, out);

    const int ln_blocks = (total + 7) / 8;
    ln_kernel<<<ln_blocks, 256>>>(h0, h1, h2, h3, n0, n1, n2, n3, gamma, beta, out);
}

// round 2
// speedup vs baseline: 1.1640x; 1.1640x over previous
#include <cuda_runtime.h>

#define D 1024
#define D4 (D / 4)
#define NB_SUM 512
#define LN_EPS 1e-5f

// Scratch (allocation-free)
__device__ float g_partial[D * NB_SUM];   // [col][block] transposed partials
__device__ float g_mean[D];
__device__ float g_global[D];
__device__ float g_v[D];
__device__ float g_attn[D];

// Software grid barrier state (reset by reset_kernel after every chain run)
__device__ unsigned g_count = 0;
__device__ volatile unsigned g_release = 0;

// ---------------------------------------------------------------------------
// helpers
// ---------------------------------------------------------------------------
__device__ __forceinline__ const float4* row_ptr(int r,
        const float* __restrict__ h0, const float* __restrict__ h1,
        const float* __restrict__ h2, const float* __restrict__ h3,
        int n0, int n01, int n012) {
    const float* p; int rr;
    if (r < n0)        { p = h0; rr = r; }
    else if (r < n01)  { p = h1; rr = r - n0; }
    else if (r < n012) { p = h2; rr = r - n01; }
    else               { p = h3; rr = r - n012; }
    return reinterpret_cast<const float4*>(p + (size_t)rr * D);
}

__device__ __forceinline__ void grid_sync(unsigned phase, unsigned nblocks) {
    __syncthreads();
    if (threadIdx.x == 0) {
        __threadfence();
        unsigned prev = atomicAdd(&g_count, 1u);
        if (prev + 1u == phase * nblocks) {
            __threadfence();
            g_release = phase;          // last arrival releases everyone
        } else {
            while (g_release < phase) __nanosleep(32);
        }
        __threadfence();
    }
    __syncthreads();
}

// ---------------------------------------------------------------------------
// Kernel 1: streaming partial column sums. Unroll-4 rows for MLP, __ldcs
// (evict-first: 400MB touched once).
// ---------------------------------------------------------------------------
__global__ void __launch_bounds__(256) colsum_kernel(
        const float* __restrict__ h0, const float* __restrict__ h1,
        const float* __restrict__ h2, const float* __restrict__ h3,
        int n0, int n1, int n2, int n3) {
    const int n01 = n0 + n1, n012 = n01 + n2;
    const int total = n012 + n3;
    const int rows_per_block = (total + gridDim.x - 1) / gridDim.x;
    const int r_begin = blockIdx.x * rows_per_block;
    const int r_end   = min(r_begin + rows_per_block, total);
    const int c4 = threadIdx.x;

    float4 a0 = make_float4(0,0,0,0), a1 = a0, a2 = a0, a3 = a0;

    int r = r_begin;
    for (; r + 4 <= r_end; r += 4) {
        float4 v0 = __ldcs(row_ptr(r,     h0,h1,h2,h3, n0,n01,n012) + c4);
        float4 v1 = __ldcs(row_ptr(r + 1, h0,h1,h2,h3, n0,n01,n012) + c4);
        float4 v2 = __ldcs(row_ptr(r + 2, h0,h1,h2,h3, n0,n01,n012) + c4);
        float4 v3 = __ldcs(row_ptr(r + 3, h0,h1,h2,h3, n0,n01,n012) + c4);
        a0.x += v0.x; a0.y += v0.y; a0.z += v0.z; a0.w += v0.w;
        a1.x += v1.x; a1.y += v1.y; a1.z += v1.z; a1.w += v1.w;
        a2.x += v2.x; a2.y += v2.y; a2.z += v2.z; a2.w += v2.w;
        a3.x += v3.x; a3.y += v3.y; a3.z += v3.z; a3.w += v3.w;
    }
    for (; r < r_end; ++r) {
        float4 v = __ldcs(row_ptr(r, h0,h1,h2,h3, n0,n01,n012) + c4);
        a0.x += v.x; a0.y += v.y; a0.z += v.z; a0.w += v.w;
    }
    a0.x += a1.x + a2.x + a3.x;
    a0.y += a1.y + a2.y + a3.y;
    a0.z += a1.z + a2.z + a3.z;
    a0.w += a1.w + a2.w + a3.w;

    const int col = c4 * 4;
    g_partial[(size_t)(col + 0) * NB_SUM + blockIdx.x] = a0.x;
    g_partial[(size_t)(col + 1) * NB_SUM + blockIdx.x] = a0.y;
    g_partial[(size_t)(col + 2) * NB_SUM + blockIdx.x] = a0.z;
    g_partial[(size_t)(col + 3) * NB_SUM + blockIdx.x] = a0.w;
}

// ---------------------------------------------------------------------------
// Kernel 2 (fused): reduce -> gemv(Wp) -> gemv(Wv) -> gemv(Wo) in ONE launch
// using a software grid barrier. 1024 blocks x 256 threads, all co-resident
// (__launch_bounds__(256, 8): 148 SMs x 8 = 1184 >= 1024).
// ---------------------------------------------------------------------------
__device__ __forceinline__ void gemv_phase(
        const float* __restrict__ W, const float* __restrict__ b,
        const float* __restrict__ x, float* __restrict__ y,
        int row, int tid, float* ws, float* out01) {
    const float4 w  = reinterpret_cast<const float4*>(W + (size_t)row * D)[tid];
    const float4 xx = reinterpret_cast<const float4*>(x)[tid];
    float s = w.x * xx.x + w.y * xx.y + w.z * xx.z + w.w * xx.w;
    #pragma unroll
    for (int o = 16; o > 0; o >>= 1) s += __shfl_xor_sync(0xFFFFFFFFu, s, o);
    if ((tid & 31) == 0) ws[tid >> 5] = s;
    __syncthreads();
    if (tid == 0) {
        float t = 0.f;
        #pragma unroll
        for (int w8 = 0; w8 < 8; ++w8) t += ws[w8];
        t += b[row];
        y[row] = t;
        if (out01) out01[row] = t;
    }
}

__global__ void __launch_bounds__(256, 8) chain_kernel(
        const float* __restrict__ Wp, const float* __restrict__ bp,
        const float* __restrict__ Wv, const float* __restrict__ bv,
        const float* __restrict__ Wo, const float* __restrict__ bo,
        float* __restrict__ out, int total_rows) {
    const int row = blockIdx.x;       // 0..1023
    const int tid = threadIdx.x;      // 0..255
    __shared__ float ws[8];
    const unsigned nb = gridDim.x;

    // Phase A: reduce 512 partials for column `row` -> mean
    {
        const float* p = g_partial + (size_t)row * NB_SUM;
        float s = p[tid] + p[tid + 256];
        #pragma unroll
        for (int o = 16; o > 0; o >>= 1) s += __shfl_xor_sync(0xFFFFFFFFu, s, o);
        if ((tid & 31) == 0) ws[tid >> 5] = s;
        __syncthreads();
        if (tid == 0) {
            float t = 0.f;
            #pragma unroll
            for (int w8 = 0; w8 < 8; ++w8) t += ws[w8];
            g_mean[row] = t / (float)total_rows;
        }
    }
    grid_sync(1, nb);
    gemv_phase(Wp, bp, g_mean,   g_global, row, tid, ws, out);  // also d_out[0:1024]
    grid_sync(2, nb);
    gemv_phase(Wv, bv, g_global, g_v,      row, tid, ws, nullptr);
    grid_sync(3, nb);
    gemv_phase(Wo, bo, g_v,      g_attn,   row, tid, ws, nullptr);
}

// Re-zero barrier state for the next graph replay.
__global__ void reset_kernel() {
    g_count = 0;
    g_release = 0;
}

// ---------------------------------------------------------------------------
// Kernel 3: LayerNorm(h + attn). Warp-per-row, streaming loads/stores.
// ---------------------------------------------------------------------------
__global__ void __launch_bounds__(256) ln_kernel(
        const float* __restrict__ h0, const float* __restrict__ h1,
        const float* __restrict__ h2, const float* __restrict__ h3,
        int n0, int n1, int n2, int n3,
        const float* __restrict__ gamma, const float* __restrict__ beta,
        float* __restrict__ out) {
    const int warp = threadIdx.x >> 5;
    const int lane = threadIdx.x & 31;
    const int n01 = n0 + n1, n012 = n01 + n2;
    const int total = n012 + n3;
    const int g = blockIdx.x * 8 + warp;
    if (g >= total) return;

    const float4* row  = row_ptr(g, h0,h1,h2,h3, n0,n01,n012);
    const float4* attn = reinterpret_cast<const float4*>(g_attn);

    float4 xs[8];
    float sum = 0.f, sumsq = 0.f;
    #pragma unroll
    for (int k = 0; k < 8; ++k) {
        const int idx = lane + 32 * k;
        float4 v = __ldcs(row + idx);
        float4 a = attn[idx];
        v.x += a.x; v.y += a.y; v.z += a.z; v.w += a.w;
        xs[k] = v;
        sum   += v.x + v.y + v.z + v.w;
        sumsq += v.x * v.x + v.y * v.y + v.z * v.z + v.w * v.w;
    }
    #pragma unroll
    for (int o = 16; o > 0; o >>= 1) {
        sum   += __shfl_xor_sync(0xFFFFFFFFu, sum,   o);
        sumsq += __shfl_xor_sync(0xFFFFFFFFu, sumsq, o);
    }

    const float inv_d = 1.f / (float)D;
    const float mean = sum * inv_d;
    const float var  = sumsq * inv_d - mean * mean;
    const float rstd = rsqrtf(var + LN_EPS);

    const float4* gm4 = reinterpret_cast<const float4*>(gamma);
    const float4* bt4 = reinterpret_cast<const float4*>(beta);
    float4* orow = reinterpret_cast<float4*>(out + D + (size_t)g * D);

    #pragma unroll
    for (int k = 0; k < 8; ++k) {
        const int idx = lane + 32 * k;
        float4 gmv = gm4[idx];
        float4 btv = bt4[idx];
        float4 v = xs[k];
        v.x = (v.x - mean) * rstd * gmv.x + btv.x;
        v.y = (v.y - mean) * rstd * gmv.y + btv.y;
        v.z = (v.z - mean) * rstd * gmv.z + btv.z;
        v.w = (v.w - mean) * rstd * gmv.w + btv.w;
        __stcs(orow + idx, v);
    }
}

extern "C" void kernel_launch(void* const* d_in, const int* in_sizes, int n_in,
                              void* d_out, int out_size) {
    const float* h0    = (const float*)d_in[0];
    const float* h1    = (const float*)d_in[1];
    const float* h2    = (const float*)d_in[2];
    const float* h3    = (const float*)d_in[3];
    const float* Wp    = (const float*)d_in[4];
    const float* bp    = (const float*)d_in[5];
    const float* Wv    = (const float*)d_in[6];
    const float* bv    = (const float*)d_in[7];
    const float* Wo    = (const float*)d_in[8];
    const float* bo    = (const float*)d_in[9];
    const float* gamma = (const float*)d_in[10];
    const float* beta  = (const float*)d_in[11];
    float* out = (float*)d_out;

    const int n0 = in_sizes[0] / D;
    const int n1 = in_sizes[1] / D;
    const int n2 = in_sizes[2] / D;
    const int n3 = in_sizes[3] / D;
    const int total = n0 + n1 + n2 + n3;

    colsum_kernel<<<NB_SUM, 256>>>(h0, h1, h2, h3, n0, n1, n2, n3);
    chain_kernel<<<D, 256>>>(Wp, bp, Wv, bv, Wo, bo, out, total);
    reset_kernel<<<1, 1>>>();
    const int ln_blocks = (total + 7) / 8;
    ln_kernel<<<ln_blocks, 256>>>(h0, h1, h2, h3, n0, n1, n2, n3, gamma, beta, out);
}